// round 4
// baseline (speedup 1.0000x reference)
#include <cuda_runtime.h>
#include <cstdint>

#define B_ 8
#define C_ 16
#define H_ 224
#define W_ 224
#define T_ 8
#define N_ 5
#define NEGV (-1e30f)
#define NTOT (B_*C_*H_*W_)
#define RB 8   // smem ring rows

// Scratch: xv = log1p(relu(x)); padded one row for unconditional prefetch.
__device__ float g_xv[NTOT + W_];

__global__ void xv_kernel(const float* __restrict__ x) {
    int n4 = NTOT / 4;
    for (int i = blockIdx.x * blockDim.x + threadIdx.x; i < n4;
         i += gridDim.x * blockDim.x) {
        float4 v = reinterpret_cast<const float4*>(x)[i];
        v.x = log1pf(fmaxf(v.x, 0.f));
        v.y = log1pf(fmaxf(v.y, 0.f));
        v.z = log1pf(fmaxf(v.z, 0.f));
        v.w = log1pf(fmaxf(v.w, 0.f));
        reinterpret_cast<float4*>(g_xv)[i] = v;
    }
}

struct Forest { int par[T_][N_]; };

union F2U { float2 f; unsigned long long u; };
__device__ __forceinline__ float2 f2add(float2 a, float2 b) {
    F2U A, B, R; A.f = a; B.f = b;
    asm("add.rn.f32x2 %0, %1, %2;" : "=l"(R.u) : "l"(A.u), "l"(B.u));
    return R.f;
}

__device__ __forceinline__ unsigned ld_acq(unsigned addr) {
    unsigned v;
    asm volatile("ld.acquire.cta.shared.u32 %0, [%1];" : "=r"(v) : "r"(addr));
    return v;
}
__device__ __forceinline__ void st_rel(unsigned addr, unsigned v) {
    asm volatile("st.release.cta.shared.u32 [%0], %1;" :: "r"(addr), "r"(v) : "memory");
}

__global__ void __launch_bounds__(64)
forest_kernel(const float* __restrict__ alphas, float* __restrict__ out, Forest f) {
    const unsigned FULL = 0xffffffffu;
    // Ring of pre-SHIFTED state vectors from warp A:
    //   s_m[0][r][w] = M3(row r)[w-1]  (NEGV at w==0)
    //   s_m[1][r][w] = M4(row r)[w-1]
    __shared__ float s_m[2][RB][W_];
    __shared__ unsigned s_fA[28];   // per-lane: A completed rows count
    __shared__ unsigned s_fB[28];   // per-lane: B completed rows count
    __shared__ float s_dummy;

    int blk = blockIdx.x;
    int t = blk & 7;
    int c = (blk >> 3) & 15;
    int b = blk >> 7;
    int warp = threadIdx.x >> 5;
    int lane = threadIdx.x & 31;

    if (threadIdx.x < 28) s_fA[threadIdx.x] = 0u;
    if (threadIdx.x >= 32 && threadIdx.x < 60) s_fB[threadIdx.x - 32] = 0u;
    __syncthreads();

    const bool act = lane < 28;
    unsigned fA_addr = (unsigned)__cvta_generic_to_shared(&s_fA[act ? lane : 0]);
    unsigned fB_addr = (unsigned)__cvta_generic_to_shared(&s_fB[act ? lane : 0]);

    const float* plane = g_xv + (size_t)(b * C_ + c) * (H_ * W_);
    const float* rowp = plane + lane * 8;

    const int p2 = f.par[t][2], p3 = f.par[t][3], p4 = f.par[t][4];
    // p1 is always 0

    // Prefetch row 0 (both warps read the same xv rows; L1/L2 hits)
    float4 c0, c1;
    if (act) {
        c0 = *reinterpret_cast<const float4*>(rowp);
        c1 = *reinterpret_cast<const float4*>(rowp + 4);
    } else {
        c0 = make_float4(NEGV, NEGV, NEGV, NEGV);
        c1 = c0;
    }

    if (warp == 0) {
        // ================= Warp A: nodes 4 and 3 =================
        float2 a4 = make_float2(alphas[(t * N_ + 4) * C_ + c], 0.f); a4.y = a4.x;
        float2 a3 = make_float2(alphas[(t * N_ + 3) * C_ + c], 0.f); a3.y = a3.x;

        float M3[8], M4[8], sh4[8];
#pragma unroll
        for (int l = 0; l < 8; l++) { M3[l] = NEGV; M4[l] = NEGV; sh4[l] = NEGV; }

        for (int h = 0; h < H_; h++) {
            const float* nrp = rowp + W_;
            float4 n0, n1;
            if (act) {
                n0 = *reinterpret_cast<const float4*>(nrp);
                n1 = *reinterpret_cast<const float4*>(nrp + 4);
            } else { n0 = make_float4(NEGV, NEGV, NEGV, NEGV); n1 = n0; }

            // Backpressure: slot (h % RB) holds row h-RB; B must have
            // finished row h-RB+1 (fB >= h-RB+2) before overwrite.
            if (h >= RB) {
                unsigned tgt = (unsigned)(h - RB + 2);
                bool done;
                do {
                    unsigned p = tgt;
                    if (act) p = ld_acq(fB_addr);
                    done = __all_sync(FULL, p >= tgt);
                } while (!done);
            }

            float xv[8] = {c0.x, c0.y, c0.z, c0.w, c1.x, c1.y, c1.z, c1.w};
            float2* xv2 = reinterpret_cast<float2*>(xv);

            float v4[8], v3[8];
#pragma unroll
            for (int k = 0; k < 4; k++) {
                reinterpret_cast<float2*>(v4)[k] = f2add(xv2[k], a4);
                reinterpret_cast<float2*>(v3)[k] = f2add(xv2[k], a3);
            }
            if (p4 == 3) {
#pragma unroll
                for (int l = 0; l < 8; l++) v3[l] += sh4[l];
            }
            // chunk prefix
#pragma unroll
            for (int l = 1; l < 8; l++) {
                v4[l] = fmaxf(v4[l], v4[l - 1]);
                v3[l] = fmaxf(v3[l], v3[l - 1]);
            }
            // row-local exclusive warp scan (2 chains interleaved)
            float e4 = __shfl_up_sync(FULL, v4[7], 1);
            float e3 = __shfl_up_sync(FULL, v3[7], 1);
            if (lane == 0) { e4 = NEGV; e3 = NEGV; }
#pragma unroll
            for (int d = 1; d < 32; d <<= 1) {
                float o4 = __shfl_up_sync(FULL, e4, d);
                float o3 = __shfl_up_sync(FULL, e3, d);
                e4 = fmaxf(e4, o4);
                e3 = fmaxf(e3, o3);
            }
            // merge
#pragma unroll
            for (int l = 0; l < 8; l++) {
                M4[l] = fmaxf(M4[l], fmaxf(v4[l], e4));
                M3[l] = fmaxf(M3[l], fmaxf(v3[l], e3));
            }
            // build shifted vectors for row h
            float b4 = __shfl_up_sync(FULL, M4[7], 1);
            float b3 = __shfl_up_sync(FULL, M3[7], 1);
            if (lane == 0) { b4 = NEGV; b3 = NEGV; }
            float sh3[8];
            sh3[0] = b3;
            sh4[0] = b4;
#pragma unroll
            for (int l = 7; l >= 1; l--) { sh3[l] = M3[l - 1]; sh4[l] = M4[l - 1]; }

            if (act) {
                float* d3 = &s_m[0][h & (RB - 1)][lane * 8];
                *reinterpret_cast<float4*>(d3) =
                    make_float4(sh3[0], sh3[1], sh3[2], sh3[3]);
                *reinterpret_cast<float4*>(d3 + 4) =
                    make_float4(sh3[4], sh3[5], sh3[6], sh3[7]);
                if (p4 != 3) {
                    float* d4 = &s_m[1][h & (RB - 1)][lane * 8];
                    *reinterpret_cast<float4*>(d4) =
                        make_float4(sh4[0], sh4[1], sh4[2], sh4[3]);
                    *reinterpret_cast<float4*>(d4 + 4) =
                        make_float4(sh4[4], sh4[5], sh4[6], sh4[7]);
                }
                st_rel(fA_addr, (unsigned)(h + 1));
            }

            c0 = n0; c1 = n1;
            rowp = nrp;
        }
        s_dummy = 0.f;  // keep smem referenced
    } else {
        // ================= Warp B: nodes 2, 1, root =================
        float2 a2 = make_float2(alphas[(t * N_ + 2) * C_ + c], 0.f); a2.y = a2.x;
        float2 a1 = make_float2(alphas[(t * N_ + 1) * C_ + c], 0.f); a1.y = a1.x;
        float2 a0 = make_float2(alphas[(t * N_ + 0) * C_ + c], 0.f); a0.y = a0.x;

        float M2[8], M1[8], sh2[8], sh1[8];
#pragma unroll
        for (int l = 0; l < 8; l++) {
            M2[l] = NEGV; M1[l] = NEGV; sh2[l] = NEGV; sh1[l] = NEGV;
        }
        float runmax = NEGV;
        const bool need4 = (p4 != 3);

        for (int h = 0; h < H_; h++) {
            const float* nrp = rowp + W_;
            float4 n0, n1;
            if (act) {
                n0 = *reinterpret_cast<const float4*>(nrp);
                n1 = *reinterpret_cast<const float4*>(nrp + 4);
            } else { n0 = make_float4(NEGV, NEGV, NEGV, NEGV); n1 = n0; }

            float ms3[8], ms4[8];
            if (h > 0) {
                unsigned tgt = (unsigned)h;  // A finished row h-1
                bool done;
                do {
                    unsigned p = tgt;
                    if (act) p = ld_acq(fA_addr);
                    done = __all_sync(FULL, p >= tgt);
                } while (!done);
                if (act) {
                    const float* q3 = &s_m[0][(h - 1) & (RB - 1)][lane * 8];
                    float4 q30 = *reinterpret_cast<const float4*>(q3);
                    float4 q31 = *reinterpret_cast<const float4*>(q3 + 4);
                    ms3[0] = q30.x; ms3[1] = q30.y; ms3[2] = q30.z; ms3[3] = q30.w;
                    ms3[4] = q31.x; ms3[5] = q31.y; ms3[6] = q31.z; ms3[7] = q31.w;
                    if (need4) {
                        const float* q4 = &s_m[1][(h - 1) & (RB - 1)][lane * 8];
                        float4 q40 = *reinterpret_cast<const float4*>(q4);
                        float4 q41 = *reinterpret_cast<const float4*>(q4 + 4);
                        ms4[0] = q40.x; ms4[1] = q40.y; ms4[2] = q40.z; ms4[3] = q40.w;
                        ms4[4] = q41.x; ms4[5] = q41.y; ms4[6] = q41.z; ms4[7] = q41.w;
                    } else {
#pragma unroll
                        for (int l = 0; l < 8; l++) ms4[l] = NEGV;
                    }
                } else {
#pragma unroll
                    for (int l = 0; l < 8; l++) { ms3[l] = NEGV; ms4[l] = NEGV; }
                }
            } else {
#pragma unroll
                for (int l = 0; l < 8; l++) { ms3[l] = NEGV; ms4[l] = NEGV; }
            }

            float xv[8] = {c0.x, c0.y, c0.z, c0.w, c1.x, c1.y, c1.z, c1.w};
            float2* xv2 = reinterpret_cast<float2*>(xv);

            float v2[8], v1[8], r0[8];
#pragma unroll
            for (int k = 0; k < 4; k++) {
                reinterpret_cast<float2*>(v2)[k] = f2add(xv2[k], a2);
                reinterpret_cast<float2*>(v1)[k] = f2add(xv2[k], a1);
                reinterpret_cast<float2*>(r0)[k] = f2add(xv2[k], a0);
            }
            if (p3 == 2) {
#pragma unroll
                for (int l = 0; l < 8; l++) v2[l] += ms3[l];
            }
            if (p4 == 2) {
#pragma unroll
                for (int l = 0; l < 8; l++) v2[l] += ms4[l];
            }
            if (p2 == 1) {
#pragma unroll
                for (int l = 0; l < 8; l++) v1[l] += sh2[l];
            }
            if (p3 == 1) {
#pragma unroll
                for (int l = 0; l < 8; l++) v1[l] += ms3[l];
            }
            if (p4 == 1) {
#pragma unroll
                for (int l = 0; l < 8; l++) v1[l] += ms4[l];
            }
            // root: node 1 always a child
#pragma unroll
            for (int l = 0; l < 8; l++) r0[l] += sh1[l];
            if (p2 == 0) {
#pragma unroll
                for (int l = 0; l < 8; l++) r0[l] += sh2[l];
            }
            if (p3 == 0) {
#pragma unroll
                for (int l = 0; l < 8; l++) r0[l] += ms3[l];
            }
            if (p4 == 0) {
#pragma unroll
                for (int l = 0; l < 8; l++) r0[l] += ms4[l];
            }
#pragma unroll
            for (int l = 0; l < 8; l++) runmax = fmaxf(runmax, r0[l]);

            // chunk prefix
#pragma unroll
            for (int l = 1; l < 8; l++) {
                v2[l] = fmaxf(v2[l], v2[l - 1]);
                v1[l] = fmaxf(v1[l], v1[l - 1]);
            }
            // row-local exclusive warp scan (2 chains)
            float e2 = __shfl_up_sync(FULL, v2[7], 1);
            float e1 = __shfl_up_sync(FULL, v1[7], 1);
            if (lane == 0) { e2 = NEGV; e1 = NEGV; }
#pragma unroll
            for (int d = 1; d < 32; d <<= 1) {
                float o2 = __shfl_up_sync(FULL, e2, d);
                float o1 = __shfl_up_sync(FULL, e1, d);
                e2 = fmaxf(e2, o2);
                e1 = fmaxf(e1, o1);
            }
#pragma unroll
            for (int l = 0; l < 8; l++) {
                M2[l] = fmaxf(M2[l], fmaxf(v2[l], e2));
                M1[l] = fmaxf(M1[l], fmaxf(v1[l], e1));
            }
            // shifted for next row
            float b2 = __shfl_up_sync(FULL, M2[7], 1);
            float b1 = __shfl_up_sync(FULL, M1[7], 1);
            if (lane == 0) { b2 = NEGV; b1 = NEGV; }
            sh2[0] = b2; sh1[0] = b1;
#pragma unroll
            for (int l = 7; l >= 1; l--) { sh2[l] = M2[l - 1]; sh1[l] = M1[l - 1]; }

            if (act) st_rel(fB_addr, (unsigned)(h + 1));

            c0 = n0; c1 = n1;
            rowp = nrp;
        }

#pragma unroll
        for (int d = 16; d; d >>= 1)
            runmax = fmaxf(runmax, __shfl_xor_sync(FULL, runmax, d));
        if (lane == 0)
            out[(b * T_ + t) * C_ + c] = expm1f(runmax);
    }
}

// ============================================================================
// Host: exact replication of np.random.default_rng(0) draws used by
// make_forest(): SeedSequence(0) -> PCG64 (XSL-RR 128/64) -> Generator
// .integers(0, i) (Lemire, buffered 32-bit path) for i = 1..4 per tree.
// ============================================================================

static inline uint32_t hashmix_(uint32_t v, uint32_t* hc) {
    v ^= *hc;
    *hc *= 0x931e8875u;   // MULT_A
    v *= *hc;
    v ^= v >> 16;
    return v;
}
static inline uint32_t mix_(uint32_t x, uint32_t y) {
    uint32_t r = x * 0xca01f9ddu - y * 0x4973f715u;  // MIX_MULT_L/R
    r ^= r >> 16;
    return r;
}

static void compute_forest(Forest* f) {
    uint32_t pool[4];
    uint32_t hc = 0x43b0d7e5u;  // INIT_A
    for (int i = 0; i < 4; i++) pool[i] = hashmix_(0u, &hc);
    for (int s = 0; s < 4; s++)
        for (int d = 0; d < 4; d++)
            if (s != d) pool[d] = mix_(pool[d], hashmix_(pool[s], &hc));

    uint32_t hb = 0x8b51f9ddu;  // INIT_B
    uint32_t w32[8];
    for (int i = 0; i < 8; i++) {
        uint32_t dv = pool[i & 3];
        dv ^= hb;
        hb *= 0x58f38dedu;  // MULT_B
        dv *= hb;
        dv ^= dv >> 16;
        w32[i] = dv;
    }
    uint64_t val[4];
    for (int i = 0; i < 4; i++)
        val[i] = (uint64_t)w32[2 * i] | ((uint64_t)w32[2 * i + 1] << 32);

    typedef unsigned __int128 u128;
    const u128 MULT = ((u128)2549297995355413924ULL << 64) | 4865540595714422341ULL;
    u128 initstate = ((u128)val[0] << 64) | (u128)val[1];
    u128 inc = (((((u128)val[2] << 64) | (u128)val[3])) << 1) | 1;
    u128 state = inc;
    state += initstate;
    state = state * MULT + inc;

    int has32 = 0;
    uint32_t cached = 0;

    for (int t = 0; t < T_; t++) {
        f->par[t][0] = -1;
        f->par[t][1] = 0;  // integers(0,1): rng==0, no draw consumed
        for (int i = 2; i < N_; i++) {
            uint32_t rng = (uint32_t)i - 1u;
            uint32_t rng_excl = rng + 1u;
            uint64_t m;
            uint32_t leftover;
            for (;;) {
                uint32_t r32;
                if (has32) {
                    has32 = 0;
                    r32 = cached;
                } else {
                    state = state * MULT + inc;
                    uint64_t hi = (uint64_t)(state >> 64);
                    uint64_t lo = (uint64_t)state;
                    unsigned rot = (unsigned)(uint64_t)(state >> 122);
                    uint64_t x = hi ^ lo;
                    uint64_t o = (x >> rot) | (x << ((64u - rot) & 63u));
                    has32 = 1;
                    cached = (uint32_t)(o >> 32);
                    r32 = (uint32_t)o;
                }
                m = (uint64_t)r32 * (uint64_t)rng_excl;
                leftover = (uint32_t)m;
                if (leftover >= rng_excl) break;
                uint32_t thr = (0xFFFFFFFFu - rng) % rng_excl;
                if (leftover >= thr) break;
            }
            f->par[t][i] = (int)(uint32_t)(m >> 32);
        }
    }
}

extern "C" void kernel_launch(void* const* d_in, const int* in_sizes, int n_in,
                              void* d_out, int out_size) {
    const float* x = (const float*)d_in[0];
    const float* alphas = (const float*)d_in[1];
    float* out = (float*)d_out;

    Forest f;
    compute_forest(&f);

    xv_kernel<<<NTOT / 4 / 256, 256>>>(x);
    forest_kernel<<<B_ * C_ * T_, 64>>>(alphas, out, f);
}